// round 6
// baseline (speedup 1.0000x reference)
#include <cuda_runtime.h>
#include <cstdint>

// Problem constants (fixed for rotary_13872744366393):
//   x: (4, 8192, 1024) f32, matrix: (64,64), thetas: (32), tscale: (1),
//   invf: (32), pairs: (32,2) int32. out: (4, 8192, 1024) f32.
#define HEADS 16
#define D     64
#define ROTN  32
#define SEQ   8192

typedef unsigned long long u64;

// B = M packed for the mainloop: g_Bp[h][kk][c] = (M[2kk][8h+c], M[2kk+1][8h+c])
// padded to 258 u64 per colg block (2064 B) for conflict-free smem LDS.128.
#define B_BLK_U64 258
__device__ u64 g_Bp[8 * B_BLK_U64];

// packed f32x2 FMA (Blackwell): d = a*b + d
#define FMA2(d, a, b) \
    asm("fma.rn.f32x2 %0, %1, %2, %0;" : "+l"(d) : "l"(a), "l"(b))

// ---------------------------------------------------------------------------
// Kernel 1: build M = G_comb @ matrix, emit packed B.
// G_comb = I @ G_0 @ ... @ G_31 ; right-multiplying by G_q updates COLUMNS:
//   col_i' = col_i*c + col_j*s ;  col_j' = -col_i*s + col_j*c
// Degenerate i==j (JAX .at sequence leaves G[i,i] = sin): col_i' = col_i*s
// ---------------------------------------------------------------------------
__global__ void build_M_kernel(const float* __restrict__ matrix,
                               const float* __restrict__ thetas,
                               const float* __restrict__ tscale,
                               const int*   __restrict__ pairs) {
    __shared__ float Gs[64][65];
    __shared__ float Mat[64][64];
    __shared__ float Msh[64][64];
    __shared__ float ssin[ROTN], scos[ROTN];
    __shared__ int   sij[ROTN][2];
    const int tid = threadIdx.x;   // 256 threads

    for (int i = tid; i < 64 * 64; i += 256)
        Mat[i >> 6][i & 63] = matrix[i];

    if (tid < ROTN) {                      // sincos once, not per-row
        const float th = thetas[tid] * tscale[0];
        float s, c;
        sincosf(th, &s, &c);
        ssin[tid] = s;
        scos[tid] = c;
        sij[tid][0] = pairs[2 * tid];
        sij[tid][1] = pairs[2 * tid + 1];
    }
    if (tid < 64) {
        #pragma unroll
        for (int k = 0; k < 64; k++) Gs[tid][k] = (tid == k) ? 1.0f : 0.0f;
    }
    __syncthreads();

    if (tid < 64) {
        for (int q = 0; q < ROTN; q++) {
            const int   i = sij[q][0];
            const int   j = sij[q][1];
            const float s = ssin[q];
            const float c = scos[q];
            const float ai = Gs[tid][i];
            const float aj = Gs[tid][j];
            if (i != j) {
                Gs[tid][i] = ai * c + aj * s;
                Gs[tid][j] = -ai * s + aj * c;
            } else {
                Gs[tid][i] = ai * s;
            }
        }
    }
    __syncthreads();

    {
        const int r  = tid >> 2;
        const int qq = tid & 3;
        float gr[64];
        #pragma unroll
        for (int k = 0; k < 64; k++) gr[k] = Gs[r][k];
        #pragma unroll
        for (int n0 = 0; n0 < 16; n0++) {
            const int n = qq * 16 + n0;
            float acc = 0.0f;
            #pragma unroll
            for (int k = 0; k < 64; k++) acc = fmaf(gr[k], Mat[k][n], acc);
            Msh[r][n] = acc;
        }
    }
    __syncthreads();

    // pack: g_Bp[h*258 + kk*8 + c] = (M[2kk][8h+c], M[2kk+1][8h+c])
    for (int idx = tid; idx < 8 * 32 * 8; idx += 256) {
        const int h  = idx >> 8;
        const int kk = (idx >> 3) & 31;
        const int c  = idx & 7;
        const int n  = 8 * h + c;
        float2 p = make_float2(Msh[2 * kk][n], Msh[2 * kk + 1][n]);
        g_Bp[h * B_BLK_U64 + kk * 8 + c] = *(const u64*)&p;
    }
}

// ---------------------------------------------------------------------------
// Kernel 2: register-tiled f32x2 GEMM (8 rows x 8 cols per thread) + RoPE.
// CTA = 128 threads, 128 rows. lane = rowg(g) x colg(h).
// ROW PERMUTATION (bank-conflict fix): thread (w,g) handles rows
//   R(r) = w*8 + g*2 + (r&1) + (r>>1)*32,  r = 0..7
// so the 4 g-lanes of an A LDS.64 sit at byte offsets g*2*264 (mod 128 =
// g*16): 4 distinct banks, conflict-free (old g*8 spacing aliased mod 128).
// Coverage of rows 0..127 is exact. smem layout itself stays row-linear.
// ---------------------------------------------------------------------------
#define A_STRIDE 264
#define SM_A     0
#define SM_B     (128 * A_STRIDE)                 // 33792
#define SM_SC    (SM_B + 8 * B_BLK_U64 * 8)       // 33792 + 16512 = 50304
#define SMEM_DYN (SM_SC + 8 * 32 * 8)             // + 2048 = 52352

__global__ __launch_bounds__(128, 3)
void rotary_f2(const float* __restrict__ x,
               const float* __restrict__ invf,
               float* __restrict__ out) {
    extern __shared__ __align__(16) char dsm[];
    float2* sc = (float2*)(dsm + SM_SC);

    const int tid  = threadIdx.x;
    const int w    = tid >> 5;
    const int lane = tid & 31;
    const int g    = lane >> 3;     // row group 0..3
    const int h    = lane & 7;      // col group 0..7

    // ---- stage A: 128 rows x 256B, coalesced LDG.128 -> 2x STS.64 ----
    {
        const uint4* xg = (const uint4*)(x + (size_t)blockIdx.x * 128 * 64);
        #pragma unroll
        for (int i = 0; i < 16; i++) {
            const int idx = i * 128 + tid;        // u128 chunk id, 2048 total
            const int row = idx >> 4;
            const int kq  = idx & 15;             // 16B chunk within row
            const uint4 v = xg[idx];
            u64* dst = (u64*)(dsm + SM_A + row * A_STRIDE + kq * 16);
            u64 lo = ((u64)v.y << 32) | v.x;
            u64 hi = ((u64)v.w << 32) | v.z;
            dst[0] = lo;
            dst[1] = hi;
        }
    }

    // ---- stage B: copy packed M (2064 u64) ----
    {
        u64* bs = (u64*)(dsm + SM_B);
        #pragma unroll
        for (int i = 0; i < 17; i++) {
            const int idx = tid + 128 * i;
            if (idx < 8 * B_BLK_U64) bs[idx] = g_Bp[idx];
        }
    }

    // ---- sincos table: 8 tokens x 32 freqs ----
    {
        #pragma unroll
        for (int e = 0; e < 2; e++) {
            const int idx = tid * 2 + e;          // 256 entries
            const int t = idx >> 5, m = idx & 31;
            const int pos = (blockIdx.x * 8 + t) & (SEQ - 1);
            float sn, cs;
            sincosf((float)pos * invf[m], &sn, &cs);
            sc[idx] = make_float2(sn, cs);
        }
    }
    __syncthreads();

    // ---- mainloop: 8x8 register tile, k-pair packed f32x2 ----
    const int rowbase = w * 8 + g * 2;            // permuted row base
    const char* abase = dsm + SM_A + rowbase * A_STRIDE;
    const char* bbase = dsm + SM_B + h * (B_BLK_U64 * 8);

    // per-r byte offsets within A (r&1 row step, (r>>1) 32-row step)
    // off[r] = ((r & 1) + (r >> 1) * 32) * A_STRIDE

    u64 acc[64];
    #pragma unroll
    for (int i = 0; i < 64; i++) acc[i] = 0ull;

    #pragma unroll 4
    for (int kk = 0; kk < 32; kk++) {
        u64 bu[8];
        #pragma unroll
        for (int j = 0; j < 4; j++) {
            const ulonglong2 b2 = *(const ulonglong2*)(bbase + kk * 64 + j * 16);
            bu[2 * j]     = b2.x;
            bu[2 * j + 1] = b2.y;
        }
        u64 au[8];
        #pragma unroll
        for (int r = 0; r < 8; r++) {
            const int off = ((r & 1) + (r >> 1) * 32) * A_STRIDE;
            au[r] = *(const u64*)(abase + off + kk * 8);
        }
        #pragma unroll
        for (int r = 0; r < 8; r++) {
            #pragma unroll
            for (int c = 0; c < 8; c++) {
                FMA2(acc[r * 8 + c], au[r], bu[c]);
            }
        }
    }

    // ---- epilogue: hsum over k halves, RoPE, *sqrt(1024)=32, STG ----
    #pragma unroll
    for (int r = 0; r < 8; r++) {
        const int row = rowbase + (r & 1) + (r >> 1) * 32;
        const int tok = row >> 4;
        float o1[4], o2[4];
        #pragma unroll
        for (int p = 0; p < 4; p++) {
            const float2 scm = sc[tok * 32 + 4 * h + p];
            const float2 a0 = *(const float2*)&acc[r * 8 + 2 * p];
            const float2 a1 = *(const float2*)&acc[r * 8 + 2 * p + 1];
            const float y1 = a0.x + a0.y;
            const float y2 = a1.x + a1.y;
            o1[p] = (y1 * scm.y - y2 * scm.x) * 32.0f;
            o2[p] = (y1 * scm.x + y2 * scm.y) * 32.0f;
        }
        float* orow = out + ((size_t)blockIdx.x * 128 + row) * 64;
        *(float4*)(orow + 4 * h)      = make_float4(o1[0], o1[1], o1[2], o1[3]);
        *(float4*)(orow + 32 + 4 * h) = make_float4(o2[0], o2[1], o2[2], o2[3]);
    }
}

// ---------------------------------------------------------------------------
extern "C" void kernel_launch(void* const* d_in, const int* in_sizes, int n_in,
                              void* d_out, int out_size) {
    const float* x      = (const float*)d_in[0];
    const float* matrix = (const float*)d_in[1];
    const float* thetas = (const float*)d_in[2];
    const float* tscale = (const float*)d_in[3];
    const float* invf   = (const float*)d_in[4];
    const int*   pairs  = (const int*)d_in[5];
    float* out = (float*)d_out;

    static bool attr_set = false;
    if (!attr_set) {
        cudaFuncSetAttribute(rotary_f2,
                             cudaFuncAttributeMaxDynamicSharedMemorySize,
                             SMEM_DYN);
        attr_set = true;
    }

    const int nrows  = in_sizes[0] / D;      // 524288
    const int blocks = nrows / 128;          // 4096

    build_M_kernel<<<1, 256>>>(matrix, thetas, tscale, pairs);
    rotary_f2<<<blocks, 128, SMEM_DYN>>>(x, invf, out);
}

// round 8
// speedup vs baseline: 1.2050x; 1.2050x over previous
#include <cuda_runtime.h>
#include <cstdint>

// Problem constants (fixed for rotary_13872744366393):
//   x: (4, 8192, 1024) f32, matrix: (64,64), thetas: (32), tscale: (1),
//   invf: (32), pairs: (32,2) int32. out: (4, 8192, 1024) f32.
#define HEADS 16
#define D     64
#define ROTN  32
#define SEQ   8192

typedef unsigned long long u64;

// B = M packed for the mainloop: g_Bp[h][kk][c] = (M[2kk][8h+c], M[2kk+1][8h+c])
// padded to 258 u64 per colg block (2064 B) for conflict-free smem LDS.128.
#define B_BLK_U64 258
__device__ u64 g_Bp[8 * B_BLK_U64];

// packed f32x2 FMA (Blackwell): d = a*b + d
#define FMA2(d, a, b) \
    asm("fma.rn.f32x2 %0, %1, %2, %0;" : "+l"(d) : "l"(a), "l"(b))

// ---------------------------------------------------------------------------
// Kernel 1: build M = G_comb @ matrix, emit packed B.
// G_comb = I @ G_0 @ ... @ G_31 ; right-multiplying by G_q updates COLUMNS:
//   col_i' = col_i*c + col_j*s ;  col_j' = -col_i*s + col_j*c
// Degenerate i==j (JAX .at sequence leaves G[i,i] = sin): col_i' = col_i*s
// ---------------------------------------------------------------------------
__global__ void build_M_kernel(const float* __restrict__ matrix,
                               const float* __restrict__ thetas,
                               const float* __restrict__ tscale,
                               const int*   __restrict__ pairs) {
    __shared__ float Gs[64][65];
    __shared__ float Mat[64][64];
    __shared__ float Msh[64][64];
    __shared__ float ssin[ROTN], scos[ROTN];
    __shared__ int   sij[ROTN][2];
    const int tid = threadIdx.x;   // 256 threads

    for (int i = tid; i < 64 * 64; i += 256)
        Mat[i >> 6][i & 63] = matrix[i];

    if (tid < ROTN) {                      // sincos once, not per-row
        const float th = thetas[tid] * tscale[0];
        float s, c;
        sincosf(th, &s, &c);
        ssin[tid] = s;
        scos[tid] = c;
        sij[tid][0] = pairs[2 * tid];
        sij[tid][1] = pairs[2 * tid + 1];
    }
    if (tid < 64) {
        #pragma unroll
        for (int k = 0; k < 64; k++) Gs[tid][k] = (tid == k) ? 1.0f : 0.0f;
    }
    __syncthreads();

    if (tid < 64) {
        for (int q = 0; q < ROTN; q++) {
            const int   i = sij[q][0];
            const int   j = sij[q][1];
            const float s = ssin[q];
            const float c = scos[q];
            const float ai = Gs[tid][i];
            const float aj = Gs[tid][j];
            if (i != j) {
                Gs[tid][i] = ai * c + aj * s;
                Gs[tid][j] = -ai * s + aj * c;
            } else {
                Gs[tid][i] = ai * s;
            }
        }
    }
    __syncthreads();

    {
        const int r  = tid >> 2;
        const int qq = tid & 3;
        float gr[64];
        #pragma unroll
        for (int k = 0; k < 64; k++) gr[k] = Gs[r][k];
        #pragma unroll
        for (int n0 = 0; n0 < 16; n0++) {
            const int n = qq * 16 + n0;
            float acc = 0.0f;
            #pragma unroll
            for (int k = 0; k < 64; k++) acc = fmaf(gr[k], Mat[k][n], acc);
            Msh[r][n] = acc;
        }
    }
    __syncthreads();

    // pack: g_Bp[h*258 + kk*8 + c] = (M[2kk][8h+c], M[2kk+1][8h+c])
    for (int idx = tid; idx < 8 * 32 * 8; idx += 256) {
        const int h  = idx >> 8;
        const int kk = (idx >> 3) & 31;
        const int c  = idx & 7;
        const int n  = 8 * h + c;
        float2 p = make_float2(Msh[2 * kk][n], Msh[2 * kk + 1][n]);
        g_Bp[h * B_BLK_U64 + kk * 8 + c] = *(const u64*)&p;
    }
}

// ---------------------------------------------------------------------------
// Kernel 2: register-tiled f32x2 GEMM (8 rows x 8 cols per thread) + RoPE.
// CTA = 128 threads, 128 rows. lane = rowg(g) x colg(h). Thread (w,g,h):
//   rows  R(r) = w*8 + g*2 + (r&1) + (r>>1)*32,  r = 0..7
//   cols  8h .. 8h+7
// A stored K-MAJOR: A_sm[kk][row] (one u64 pair per row), stride 1040 B per
// kk-plane (MULTIPLE OF 16 — R7 used 1032 and odd kk-planes misaligned the
// LDS.128). Rows (R, R+1) are 16B-adjacent => 4x LDS.128 covers all 8 A
// operands. Lane banking: g-lanes at +16B (4 distinct banks), h-lanes
// broadcast. B packed per colg block (2064 B): 4x LDS.128, h-lanes at
// h*2064 (mod 128 = h*16) -> conflict-free.
// __launch_bounds__(128, 2): 256-reg budget enables explicit double-buffer
// software pipelining (R6 was stall-bound at the 170-reg ceiling).
// ---------------------------------------------------------------------------
#define A_K_STRIDE 1040
#define SM_A     0
#define SM_B     (32 * A_K_STRIDE)                // 33280
#define SM_SC    (SM_B + 8 * B_BLK_U64 * 8)       // 33280 + 16512 = 49792
#define SMEM_DYN (SM_SC + 8 * 32 * 8)             // + 2048 = 51840

__global__ __launch_bounds__(128, 2)
void rotary_f2(const float* __restrict__ x,
               const float* __restrict__ invf,
               float* __restrict__ out) {
    extern __shared__ __align__(16) char dsm[];
    float2* sc = (float2*)(dsm + SM_SC);

    const int tid  = threadIdx.x;
    const int w    = tid >> 5;
    const int lane = tid & 31;
    const int g    = lane >> 3;     // row group 0..3
    const int h    = lane & 7;      // col group 0..7

    // ---- stage A: 128 rows x 256B, coalesced LDG.128 -> 2x STS.64 k-major ----
    {
        const uint4* xg = (const uint4*)(x + (size_t)blockIdx.x * 128 * 64);
        #pragma unroll
        for (int i = 0; i < 16; i++) {
            const int idx = i * 128 + tid;        // u128 chunk id, 2048 total
            const int row = idx >> 4;
            const int kq  = idx & 15;             // 16B chunk within row
            const uint4 v = xg[idx];
            const u64 lo = ((u64)v.y << 32) | v.x;   // k-pair 2kq
            const u64 hi = ((u64)v.w << 32) | v.z;   // k-pair 2kq+1
            char* base = dsm + SM_A + row * 8;
            *(u64*)(base + (2 * kq)     * A_K_STRIDE) = lo;
            *(u64*)(base + (2 * kq + 1) * A_K_STRIDE) = hi;
        }
    }

    // ---- stage B: copy packed M (2064 u64) ----
    {
        u64* bs = (u64*)(dsm + SM_B);
        #pragma unroll
        for (int i = 0; i < 17; i++) {
            const int idx = tid + 128 * i;
            if (idx < 8 * B_BLK_U64) bs[idx] = g_Bp[idx];
        }
    }

    // ---- sincos table: 8 tokens x 32 freqs ----
    {
        #pragma unroll
        for (int e = 0; e < 2; e++) {
            const int idx = tid * 2 + e;          // 256 entries
            const int t = idx >> 5, m = idx & 31;
            const int pos = (blockIdx.x * 8 + t) & (SEQ - 1);
            float sn, cs;
            sincosf((float)pos * invf[m], &sn, &cs);
            sc[idx] = make_float2(sn, cs);
        }
    }
    __syncthreads();

    // ---- mainloop: 8x8 register tile, explicit double-buffered loads ----
    const int rowbase = w * 8 + g * 2;
    const char* abase = dsm + SM_A + rowbase * 8;
    const char* bbase = dsm + SM_B + h * (B_BLK_U64 * 8);

    u64 acc[64];
    #pragma unroll
    for (int i = 0; i < 64; i++) acc[i] = 0ull;

    u64 au[2][8], bu[2][8];

    // prefetch kk = 0
    #pragma unroll
    for (int j = 0; j < 4; j++) {
        const ulonglong2 a2 = *(const ulonglong2*)(abase + j * 256);
        au[0][2 * j] = a2.x;  au[0][2 * j + 1] = a2.y;
        const ulonglong2 b2 = *(const ulonglong2*)(bbase + j * 16);
        bu[0][2 * j] = b2.x;  bu[0][2 * j + 1] = b2.y;
    }

    #pragma unroll 4
    for (int kk = 0; kk < 32; kk++) {
        const int cur = kk & 1, nxt = cur ^ 1;
        if (kk < 31) {
            const char* ap = abase + (kk + 1) * A_K_STRIDE;
            const char* bp = bbase + (kk + 1) * 64;
            #pragma unroll
            for (int j = 0; j < 4; j++) {
                const ulonglong2 a2 = *(const ulonglong2*)(ap + j * 256);
                au[nxt][2 * j] = a2.x;  au[nxt][2 * j + 1] = a2.y;
                const ulonglong2 b2 = *(const ulonglong2*)(bp + j * 16);
                bu[nxt][2 * j] = b2.x;  bu[nxt][2 * j + 1] = b2.y;
            }
        }
        #pragma unroll
        for (int r = 0; r < 8; r++) {
            #pragma unroll
            for (int c = 0; c < 8; c++) {
                FMA2(acc[r * 8 + c], au[cur][r], bu[cur][c]);
            }
        }
    }

    // ---- epilogue: hsum over k halves, RoPE, *sqrt(1024)=32, STG ----
    #pragma unroll
    for (int r = 0; r < 8; r++) {
        const int row = rowbase + (r & 1) + (r >> 1) * 32;
        const int tok = row >> 4;
        float o1[4], o2[4];
        #pragma unroll
        for (int p = 0; p < 4; p++) {
            const float2 scm = sc[tok * 32 + 4 * h + p];
            const float2 a0 = *(const float2*)&acc[r * 8 + 2 * p];
            const float2 a1 = *(const float2*)&acc[r * 8 + 2 * p + 1];
            const float y1 = a0.x + a0.y;
            const float y2 = a1.x + a1.y;
            o1[p] = (y1 * scm.y - y2 * scm.x) * 32.0f;
            o2[p] = (y1 * scm.x + y2 * scm.y) * 32.0f;
        }
        float* orow = out + ((size_t)blockIdx.x * 128 + row) * 64;
        *(float4*)(orow + 4 * h)      = make_float4(o1[0], o1[1], o1[2], o1[3]);
        *(float4*)(orow + 32 + 4 * h) = make_float4(o2[0], o2[1], o2[2], o2[3]);
    }
}

// ---------------------------------------------------------------------------
extern "C" void kernel_launch(void* const* d_in, const int* in_sizes, int n_in,
                              void* d_out, int out_size) {
    const float* x      = (const float*)d_in[0];
    const float* matrix = (const float*)d_in[1];
    const float* thetas = (const float*)d_in[2];
    const float* tscale = (const float*)d_in[3];
    const float* invf   = (const float*)d_in[4];
    const int*   pairs  = (const int*)d_in[5];
    float* out = (float*)d_out;

    static bool attr_set = false;
    if (!attr_set) {
        cudaFuncSetAttribute(rotary_f2,
                             cudaFuncAttributeMaxDynamicSharedMemorySize,
                             SMEM_DYN);
        attr_set = true;
    }

    const int nrows  = in_sizes[0] / D;      // 524288
    const int blocks = nrows / 128;          // 4096

    build_M_kernel<<<1, 256>>>(matrix, thetas, tscale, pairs);
    rotary_f2<<<blocks, 128, SMEM_DYN>>>(x, invf, out);
}